// round 1
// baseline (speedup 1.0000x reference)
#include <cuda_runtime.h>

// Problem constants
#define BX 2
#define CX 8
#define BC 16                 // B*C fused channel count
#define FX 80
#define NX 128
#define HH 512
#define WW 1024
#define M  (FX * NX * NX)     // 1310720 texels per channel
#define HW (HH * WW)          // 524288 pixels

// Scratch: x transposed to [M][BC] so one texel's 16 channels are contiguous (64B).
// __device__ global (no cudaMalloc allowed).
__device__ __align__(128) float g_xt[(size_t)M * BC];

// ---------------------------------------------------------------------------
// Pass 1: transpose x[16][M] -> g_xt[M][16].
// Block = 512 threads handles a 16(ch) x 128(m) tile.
// Load side: warp r loads 128 consecutive floats of channel r via float4 (coalesced).
// Store side: thread writes one float4 = 4 channels of one m-row (16B), block
// writes 128*16 floats = 8KB contiguous (fully coalesced).
// ---------------------------------------------------------------------------
__global__ void __launch_bounds__(512) transpose_kernel(const float* __restrict__ x) {
    __shared__ float4 s4[16][33];   // padded: row stride 33 float4 = 132 floats

    const int m0 = blockIdx.x * 128;
    const int r  = threadIdx.x >> 5;   // channel 0..15 (one warp per channel row)
    const int jv = threadIdx.x & 31;   // float4 column group 0..31

    const float4* src = reinterpret_cast<const float4*>(x + (size_t)r * M + m0);
    s4[r][jv] = src[jv];               // STS.128, conflict-free
    __syncthreads();

    const int ml = threadIdx.x >> 2;          // local m 0..127
    const int c0 = (threadIdx.x & 3) << 2;    // channel base 0,4,8,12
    const float* sf = reinterpret_cast<const float*>(&s4[0][0]);
    // element (channel c, col ml) lives at sf[c*132 + ml]
    float4 w;
    w.x = sf[(c0 + 0) * 132 + ml];
    w.y = sf[(c0 + 1) * 132 + ml];
    w.z = sf[(c0 + 2) * 132 + ml];
    w.w = sf[(c0 + 3) * 132 + ml];

    float4* dst = reinterpret_cast<float4*>(g_xt + (size_t)(m0 + ml) * BC + c0);
    *dst = w;                          // STG.128, block-contiguous
}

// ---------------------------------------------------------------------------
// Pass 2: bilinear gather. Block = 512 threads = 32 pixels x 16 channels.
// Gather phase: 16 consecutive threads (one pixel) read 16 consecutive floats
// per texel -> each LDG is an aligned, fully-used 64B chunk (index multiple of
// 16 floats => 64B aligned). g00/g01 regions are one contiguous 128B line.
// Store phase: smem-retile so each warp writes 32 consecutive pixels (128B)
// within one output channel plane.
// ---------------------------------------------------------------------------
__global__ void __launch_bounds__(512) sample_kernel(const int*   __restrict__ quad,
                                                     const float* __restrict__ uv,
                                                     float*       __restrict__ out) {
    __shared__ float s[16][33];        // 16 channels x 32 pixels (+pad)

    const int t    = threadIdx.x;
    const int p    = t >> 4;           // pixel-in-tile 0..31
    const int c    = t & 15;           // channel 0..15
    const int pix  = blockIdx.x * 32 + p;

    const float u = uv[2 * pix + 0];
    const float v = uv[2 * pix + 1];
    const int   f = quad[pix];

    // match reference: u0 = clip(floor(u), 0, N-2); du = u - u0
    int u0 = (int)floorf(u);
    int v0 = (int)floorf(v);
    u0 = min(max(u0, 0), NX - 2);
    v0 = min(max(v0, 0), NX - 2);
    const float du = u - (float)u0;
    const float dv = v - (float)v0;

    const float* base = g_xt + ((size_t)((f * NX + v0) * NX + u0)) * BC + c;
    const float g00 = base[0];
    const float g01 = base[BC];
    const float g10 = base[BC * NX];
    const float g11 = base[BC * NX + BC];

    const float w00 = (1.0f - du) * (1.0f - dv);
    const float w01 = du * (1.0f - dv);
    const float w10 = (1.0f - du) * dv;
    const float w11 = du * dv;
    const float res = g00 * w00 + g01 * w01 + g10 * w10 + g11 * w11;

    s[c][p] = res;
    __syncthreads();

    const int c2 = t >> 5;             // channel plane 0..15
    const int p2 = t & 31;             // pixel 0..31
    out[(size_t)c2 * HW + (size_t)blockIdx.x * 32 + p2] = s[c2][p2];
}

extern "C" void kernel_launch(void* const* d_in, const int* in_sizes, int n_in,
                              void* d_out, int out_size) {
    const float* x    = (const float*)d_in[0];   // [2,8,80,128,128] fp32
    const int*   quad = (const int*)  d_in[1];   // [512,1024] int32
    const float* uv   = (const float*)d_in[2];   // [512,1024,2] fp32
    float*       out  = (float*)d_out;           // [2,8,512,1024] fp32

    transpose_kernel<<<M / 128, 512>>>(x);       // 10240 blocks
    sample_kernel<<<HW / 32, 512>>>(quad, uv, out); // 16384 blocks
}

// round 2
// speedup vs baseline: 1.7284x; 1.7284x over previous
#include <cuda_runtime.h>
#include <cuda_fp16.h>

// Problem constants
#define FX 80
#define NX 128
#define HH 512
#define WW 1024
#define BC 16                 // B*C fused channel count
#define M  (FX * NX * NX)     // 1310720 texels per channel
#define HW (HH * WW)          // 524288 pixels

// Scratch: x transposed + converted to fp16, layout [M][16] halfs (32B/texel).
// Whole table = 40MB -> fits in the 126MB L2.
__device__ __align__(128) __half g_xt[(size_t)M * BC];

// ---------------------------------------------------------------------------
// Pass 1: transpose x[16][M] (fp32) -> g_xt[M][16] (fp16).
// Block = 512 threads handles a 16(ch) x 128(m) tile.
// Load: warp r loads 128 consecutive floats of channel r via float4 (coalesced).
// Store: thread converts 4 channels of one m-row to 4 halfs, STG.64;
// 4 consecutive threads cover one 32B row; block writes 4KB contiguous.
// ---------------------------------------------------------------------------
__global__ void __launch_bounds__(512) transpose_kernel(const float* __restrict__ x) {
    __shared__ float4 s4[16][33];   // padded: row stride 33 float4 = 132 floats

    const int m0 = blockIdx.x * 128;
    const int r  = threadIdx.x >> 5;   // channel 0..15
    const int jv = threadIdx.x & 31;   // float4 column 0..31

    const float4* src = reinterpret_cast<const float4*>(x + (size_t)r * M + m0);
    s4[r][jv] = src[jv];
    __syncthreads();

    const int ml = threadIdx.x >> 2;          // local m 0..127
    const int q  = threadIdx.x & 3;           // channel quad 0..3
    const float* sf = reinterpret_cast<const float*>(&s4[0][0]);
    const float a = sf[(4 * q + 0) * 132 + ml];
    const float b = sf[(4 * q + 1) * 132 + ml];
    const float c = sf[(4 * q + 2) * 132 + ml];
    const float d = sf[(4 * q + 3) * 132 + ml];
    __half2 h0 = __floats2half2_rn(a, b);
    __half2 h1 = __floats2half2_rn(c, d);
    uint2 w;
    w.x = *reinterpret_cast<unsigned int*>(&h0);
    w.y = *reinterpret_cast<unsigned int*>(&h1);
    *reinterpret_cast<uint2*>(g_xt + (size_t)(m0 + ml) * BC + 4 * q) = w;  // STG.64, 8B-aligned
}

// accumulate 8 fp16 channels (one uint4) into fp32 accumulators with weight w
__device__ __forceinline__ void acc8(float* r, const uint4& a, float w) {
    const __half2* h = reinterpret_cast<const __half2*>(&a);
#pragma unroll
    for (int j = 0; j < 4; j++) {
        float2 f = __half22float2(h[j]);
        r[2 * j]     = fmaf(f.x, w, r[2 * j]);
        r[2 * j + 1] = fmaf(f.y, w, r[2 * j + 1]);
    }
}

// ---------------------------------------------------------------------------
// Pass 2: bilinear gather. Block = 256 threads = 128 pixels x 2 half-groups.
// Each thread loads 4 corners as uint4 (16B = 8 fp16 channels) -> 4 independent
// LDG.128, all 16B-aligned and fully used. g00||g01 span one contiguous 64B run.
// Results staged in smem, then written out with 128B-coalesced stores per plane.
// ---------------------------------------------------------------------------
__global__ void __launch_bounds__(256) sample_kernel(const int*   __restrict__ quad,
                                                     const float* __restrict__ uv,
                                                     float*       __restrict__ out) {
    __shared__ float s[BC][130];       // stride 130: store-stage conflict-free

    const int t   = threadIdx.x;
    const int p   = t >> 1;            // pixel-in-tile 0..127
    const int hg  = t & 1;             // half-group: channels hg*8 .. hg*8+7
    const int pix = blockIdx.x * 128 + p;

    const float2 uvp = reinterpret_cast<const float2*>(uv)[pix];
    const int    f   = quad[pix];

    int u0 = min(max((int)floorf(uvp.x), 0), NX - 2);
    int v0 = min(max((int)floorf(uvp.y), 0), NX - 2);
    const float du = uvp.x - (float)u0;
    const float dv = uvp.y - (float)v0;

    const __half* base = g_xt + ((size_t)((f * NX + v0) * NX + u0)) * BC + hg * 8;
    const uint4 a00 = *reinterpret_cast<const uint4*>(base);
    const uint4 a01 = *reinterpret_cast<const uint4*>(base + BC);
    const uint4 a10 = *reinterpret_cast<const uint4*>(base + BC * NX);
    const uint4 a11 = *reinterpret_cast<const uint4*>(base + BC * NX + BC);

    const float w00 = (1.0f - du) * (1.0f - dv);
    const float w01 = du * (1.0f - dv);
    const float w10 = (1.0f - du) * dv;
    const float w11 = du * dv;

    float r[8];
#pragma unroll
    for (int j = 0; j < 8; j++) r[j] = 0.0f;
    acc8(r, a00, w00);
    acc8(r, a01, w01);
    acc8(r, a10, w10);
    acc8(r, a11, w11);

#pragma unroll
    for (int k = 0; k < 8; k++) s[hg * 8 + k][p] = r[k];
    __syncthreads();

    const size_t obase = (size_t)blockIdx.x * 128;
#pragma unroll
    for (int i = 0; i < 8; i++) {
        const int lin = t + 256 * i;
        const int c   = lin >> 7;      // channel plane 0..15
        const int pp  = lin & 127;     // pixel 0..127 (consecutive lanes -> 128B runs)
        out[(size_t)c * HW + obase + pp] = s[c][pp];
    }
}

extern "C" void kernel_launch(void* const* d_in, const int* in_sizes, int n_in,
                              void* d_out, int out_size) {
    const float* x    = (const float*)d_in[0];   // [2,8,80,128,128] fp32
    const int*   quad = (const int*)  d_in[1];   // [512,1024] int32
    const float* uv   = (const float*)d_in[2];   // [512,1024,2] fp32
    float*       out  = (float*)d_out;           // [2,8,512,1024] fp32

    transpose_kernel<<<M / 128, 512>>>(x);            // 10240 blocks
    sample_kernel<<<HW / 128, 256>>>(quad, uv, out);  // 4096 blocks
}

// round 3
// speedup vs baseline: 2.0140x; 1.1652x over previous
#include <cuda_runtime.h>
#include <cuda_fp16.h>

// Problem constants
#define FX 80
#define NX 128
#define HH 512
#define WW 1024
#define BC 16                 // B*C fused channel count
#define M  (FX * NX * NX)     // 1310720 texels per channel
#define HW (HH * WW)          // 524288 pixels

// Scratch: x transposed + converted to fp16, layout [M][16] halfs (32B/texel).
__device__ __align__(128) __half g_xt[(size_t)M * BC];

__device__ __forceinline__ unsigned int h2u(__half2 h) {
    return *reinterpret_cast<unsigned int*>(&h);
}

// ---------------------------------------------------------------------------
// Pass 1: fused transpose+convert, NO shared memory.
// Warp does 16 coalesced scalar loads (one per channel); after the loop,
// lane t holds texel (m0+t)'s 16 channels in registers -> convert to 8 half2,
// write 32B via 2 STG.128. MLP=16, no barriers.
// ---------------------------------------------------------------------------
__global__ void __launch_bounds__(256) transpose_kernel(const float* __restrict__ x) {
    const int m = blockIdx.x * 256 + threadIdx.x;   // one texel per thread

    float v[16];
#pragma unroll
    for (int c = 0; c < 16; c++)
        v[c] = __ldg(x + (size_t)c * M + m);        // 16 independent coalesced LDG.32

    unsigned int w[8];
#pragma unroll
    for (int j = 0; j < 8; j++)
        w[j] = h2u(__floats2half2_rn(v[2 * j], v[2 * j + 1]));

    uint4* dst = reinterpret_cast<uint4*>(g_xt + (size_t)m * BC);
    dst[0] = make_uint4(w[0], w[1], w[2], w[3]);
    dst[1] = make_uint4(w[4], w[5], w[6], w[7]);
}

// accumulate 8 fp16 channels (one uint4) into fp32 accumulators with weight w
__device__ __forceinline__ void acc8(float* r, const uint4& a, float w) {
    const __half2* h = reinterpret_cast<const __half2*>(&a);
#pragma unroll
    for (int j = 0; j < 4; j++) {
        float2 f = __half22float2(h[j]);
        r[2 * j]     = fmaf(f.x, w, r[2 * j]);
        r[2 * j + 1] = fmaf(f.y, w, r[2 * j + 1]);
    }
}

// ---------------------------------------------------------------------------
// Pass 2: bilinear gather, 2 pixels per thread (8 independent LDG.128).
// Block = 256 threads handles 256 pixels; thread t: pixels p and p+128,
// channels hg*8..hg*8+7. Results staged in smem, stores 1KB-coalesced per plane.
// ---------------------------------------------------------------------------
__global__ void __launch_bounds__(256) sample_kernel(const int*   __restrict__ quad,
                                                     const float* __restrict__ uv,
                                                     float*       __restrict__ out) {
    __shared__ float s[BC][258];       // stride 258: conflict-free both phases

    const int t   = threadIdx.x;
    const int p   = t >> 1;            // pixel-in-tile 0..127 (second = p+128)
    const int hg  = t & 1;             // half-group: channels hg*8 .. hg*8+7
    const int pixA = blockIdx.x * 256 + p;
    const int pixB = pixA + 128;

    const float2 uvA = reinterpret_cast<const float2*>(uv)[pixA];
    const float2 uvB = reinterpret_cast<const float2*>(uv)[pixB];
    const int fA = quad[pixA];
    const int fB = quad[pixB];

    int u0A = min(max((int)floorf(uvA.x), 0), NX - 2);
    int v0A = min(max((int)floorf(uvA.y), 0), NX - 2);
    int u0B = min(max((int)floorf(uvB.x), 0), NX - 2);
    int v0B = min(max((int)floorf(uvB.y), 0), NX - 2);
    const float duA = uvA.x - (float)u0A, dvA = uvA.y - (float)v0A;
    const float duB = uvB.x - (float)u0B, dvB = uvB.y - (float)v0B;

    const __half* baseA = g_xt + ((size_t)((fA * NX + v0A) * NX + u0A)) * BC + hg * 8;
    const __half* baseB = g_xt + ((size_t)((fB * NX + v0B) * NX + u0B)) * BC + hg * 8;

    // issue all 8 gathers up front (8 outstanding LDG.128)
    const uint4 a00 = *reinterpret_cast<const uint4*>(baseA);
    const uint4 a01 = *reinterpret_cast<const uint4*>(baseA + BC);
    const uint4 a10 = *reinterpret_cast<const uint4*>(baseA + BC * NX);
    const uint4 a11 = *reinterpret_cast<const uint4*>(baseA + BC * NX + BC);
    const uint4 b00 = *reinterpret_cast<const uint4*>(baseB);
    const uint4 b01 = *reinterpret_cast<const uint4*>(baseB + BC);
    const uint4 b10 = *reinterpret_cast<const uint4*>(baseB + BC * NX);
    const uint4 b11 = *reinterpret_cast<const uint4*>(baseB + BC * NX + BC);

    float rA[8], rB[8];
#pragma unroll
    for (int j = 0; j < 8; j++) { rA[j] = 0.0f; rB[j] = 0.0f; }

    {
        const float w00 = (1.0f - duA) * (1.0f - dvA);
        const float w01 = duA * (1.0f - dvA);
        const float w10 = (1.0f - duA) * dvA;
        const float w11 = duA * dvA;
        acc8(rA, a00, w00); acc8(rA, a01, w01);
        acc8(rA, a10, w10); acc8(rA, a11, w11);
    }
    {
        const float w00 = (1.0f - duB) * (1.0f - dvB);
        const float w01 = duB * (1.0f - dvB);
        const float w10 = (1.0f - duB) * dvB;
        const float w11 = duB * dvB;
        acc8(rB, b00, w00); acc8(rB, b01, w01);
        acc8(rB, b10, w10); acc8(rB, b11, w11);
    }

#pragma unroll
    for (int k = 0; k < 8; k++) {
        s[hg * 8 + k][p]       = rA[k];
        s[hg * 8 + k][p + 128] = rB[k];
    }
    __syncthreads();

    const size_t obase = (size_t)blockIdx.x * 256;
#pragma unroll
    for (int c = 0; c < BC; c++)
        out[(size_t)c * HW + obase + t] = s[c][t];   // 1KB coalesced per plane
}

extern "C" void kernel_launch(void* const* d_in, const int* in_sizes, int n_in,
                              void* d_out, int out_size) {
    const float* x    = (const float*)d_in[0];   // [2,8,80,128,128] fp32
    const int*   quad = (const int*)  d_in[1];   // [512,1024] int32
    const float* uv   = (const float*)d_in[2];   // [512,1024,2] fp32
    float*       out  = (float*)d_out;           // [2,8,512,1024] fp32

    transpose_kernel<<<M / 256, 256>>>(x);            // 5120 blocks
    sample_kernel<<<HW / 256, 256>>>(quad, uv, out);  // 2048 blocks
}